// round 8
// baseline (speedup 1.0000x reference)
#include <cuda_runtime.h>
#include <stdint.h>

#define DIM 64
#define WARPS_PER_BLOCK 8
#define THREADS (WARPS_PER_BLOCK * 32)
#define EDGES_PER_WARP 8   // 2 lane-groups x 4 edges per thread

__global__ void zero_kernel4(float4* __restrict__ h, int n4) {
    int i = blockIdx.x * blockDim.x + threadIdx.x;
    if (i < n4) h[i] = make_float4(0.f, 0.f, 0.f, 0.f);
}

__device__ __forceinline__ void red_v4(float* p, float s,
                                       float m0, float m1, float m2, float m3) {
    asm volatile("red.global.add.v4.f32 [%0], {%1, %2, %3, %4};"
                 :: "l"(p), "f"(s * m0), "f"(s * m1), "f"(s * m2), "f"(s * m3)
                 : "memory");
}

__global__ __launch_bounds__(THREADS)
void distmult_edge_kernel(const float* __restrict__ node_emb,
                          const float* __restrict__ edge_emb,
                          const int* __restrict__ src,
                          const int* __restrict__ dst,
                          float* __restrict__ h_out,
                          float* __restrict__ dr_out,
                          int n_edges) {
    int warp_id = blockIdx.x * WARPS_PER_BLOCK + (threadIdx.x >> 5);
    int lane    = threadIdx.x & 31;
    int half    = lane >> 4;
    int l       = lane & 15;

    int ebase = warp_id * EDGES_PER_WARP + half;

    int e[4], ec[4];
    bool v[4];
    #pragma unroll
    for (int i = 0; i < 4; i++) {
        e[i]  = ebase + 2 * i;
        v[i]  = e[i] < n_edges;
        ec[i] = v[i] ? e[i] : n_edges - 1;   // clamp; predicate only stores
    }

    // ---- batched index loads: 8 independent LDGs ----
    int s[4], d[4];
    #pragma unroll
    for (int i = 0; i < 4; i++) {
        s[i] = src[ec[i]];
        d[i] = dst[ec[i]];
    }

    // ---- batched vector loads: 12 LDG.128 ----
    float4 hh[4], rr[4], tt[4];
    #pragma unroll
    for (int i = 0; i < 4; i++) {
        hh[i] = reinterpret_cast<const float4*>(node_emb + (long long)s[i]  * DIM)[l];
        rr[i] = reinterpret_cast<const float4*>(edge_emb + (long long)ec[i] * DIM)[l];
        tt[i] = reinterpret_cast<const float4*>(node_emb + (long long)d[i]  * DIM)[l];
    }

    // ---- per-edge partial dot + trans ----
    float t0[4], t1[4], t2[4], t3[4], p[4];
    #pragma unroll
    for (int i = 0; i < 4; i++) {
        t0[i] = hh[i].x * rr[i].x;
        t1[i] = hh[i].y * rr[i].y;
        t2[i] = hh[i].z * rr[i].z;
        t3[i] = hh[i].w * rr[i].w;
        float q = t0[i] * tt[i].x;
        q = fmaf(t1[i], tt[i].y, q);
        q = fmaf(t2[i], tt[i].z, q);
        q = fmaf(t3[i], tt[i].w, q);
        p[i] = q;
    }

    // ---- four independent width-16 reductions, interleaved ----
    #pragma unroll
    for (int o = 8; o > 0; o >>= 1) {
        #pragma unroll
        for (int i = 0; i < 4; i++)
            p[i] += __shfl_xor_sync(0xffffffffu, p[i], o, 16);
    }

    if (l == 0) {
        #pragma unroll
        for (int i = 0; i < 4; i++)
            if (v[i]) dr_out[e[i]] = p[i];
    }

    #pragma unroll
    for (int i = 0; i < 4; i++) {
        float sig = 1.0f / (1.0f + __expf(-p[i]));
        if (v[i]) {
            float* hd = h_out + (long long)d[i] * DIM + 4 * l;
            red_v4(hd, sig, t0[i], t1[i], t2[i], t3[i]);
        }
    }
}

extern "C" void kernel_launch(void* const* d_in, const int* in_sizes, int n_in,
                              void* d_out, int out_size) {
    const float* node_emb = (const float*)d_in[0];
    const float* edge_emb = (const float*)d_in[1];
    const int*   src      = (const int*)d_in[2];
    const int*   dst      = (const int*)d_in[3];

    int n_nodes = in_sizes[0] / DIM;
    int n_edges = in_sizes[1] / DIM;

    float* h_out  = (float*)d_out;                                // [N, D]
    float* dr_out = (float*)d_out + (long long)n_nodes * DIM;     // [E]

    int h4 = n_nodes * DIM / 4;
    zero_kernel4<<<(h4 + 255) / 256, 256>>>((float4*)h_out, h4);

    int edges_per_block = WARPS_PER_BLOCK * EDGES_PER_WARP;
    int blocks = (n_edges + edges_per_block - 1) / edges_per_block;
    distmult_edge_kernel<<<blocks, THREADS>>>(node_emb, edge_emb, src, dst,
                                              h_out, dr_out, n_edges);
}

// round 9
// speedup vs baseline: 1.6771x; 1.6771x over previous
#include <cuda_runtime.h>
#include <stdint.h>

#define DIM 64
#define WARPS_PER_BLOCK 8
#define THREADS (WARPS_PER_BLOCK * 32)
#define EDGES_PER_WARP 4   // 4 groups of 8 lanes, one edge per group

__global__ void zero_kernel4(float4* __restrict__ h, int n4) {
    int i = blockIdx.x * blockDim.x + threadIdx.x;
    if (i < n4) h[i] = make_float4(0.f, 0.f, 0.f, 0.f);
}

__global__ __launch_bounds__(THREADS)
void distmult_edge_kernel(const float* __restrict__ node_emb,
                          const float* __restrict__ edge_emb,
                          const int* __restrict__ src,
                          const int* __restrict__ dst,
                          float* __restrict__ h_out,
                          float* __restrict__ dr_out,
                          int n_edges) {
    int warp_id = blockIdx.x * WARPS_PER_BLOCK + (threadIdx.x >> 5);
    int lane    = threadIdx.x & 31;
    int g       = lane >> 3;        // group (edge slot) within warp: 0..3
    int l       = lane & 7;         // lane within 8-lane group

    int e  = warp_id * EDGES_PER_WARP + g;
    bool v = e < n_edges;
    int ec = v ? e : n_edges - 1;   // clamp; predicate only stores

    int s = src[ec];
    int d = dst[ec];

    // Each lane covers dims [l*4, l*4+4) and [32 + l*4, 32 + l*4+4).
    // First LDG of each operand touches the first 128B line of the row,
    // second LDG the second line — one line per edge per instruction.
    const float4* hp = reinterpret_cast<const float4*>(node_emb + (long long)s  * DIM);
    const float4* rp = reinterpret_cast<const float4*>(edge_emb + (long long)ec * DIM);
    const float4* tp = reinterpret_cast<const float4*>(node_emb + (long long)d  * DIM);

    // ---- front-batched loads: 6 independent LDG.128 ----
    float4 ha = hp[l];
    float4 hb = hp[l + 8];
    float4 ra = rp[l];
    float4 rb = rp[l + 8];
    float4 ta = tp[l];
    float4 tb = tp[l + 8];

    // trans = head * rel (kept as message payload)
    float m0 = ha.x * ra.x, m1 = ha.y * ra.y, m2 = ha.z * ra.z, m3 = ha.w * ra.w;
    float n0 = hb.x * rb.x, n1 = hb.y * rb.y, n2 = hb.z * rb.z, n3 = hb.w * rb.w;

    // partial dot over this lane's 8 dims
    float p = m0 * ta.x;
    p = fmaf(m1, ta.y, p);
    p = fmaf(m2, ta.z, p);
    p = fmaf(m3, ta.w, p);
    p = fmaf(n0, tb.x, p);
    p = fmaf(n1, tb.y, p);
    p = fmaf(n2, tb.z, p);
    p = fmaf(n3, tb.w, p);

    // width-8 butterfly reduction: 3 shuffles, 4 edges reduced per warp op
    #pragma unroll
    for (int o = 4; o > 0; o >>= 1)
        p += __shfl_xor_sync(0xffffffffu, p, o, 8);

    if (l == 0 && v) dr_out[e] = p;

    float sig = 1.0f / (1.0f + __expf(-p));

    if (v) {
        float* hd = h_out + (long long)d * DIM + 4 * l;
        asm volatile("red.global.add.v4.f32 [%0], {%1, %2, %3, %4};"
                     :: "l"(hd), "f"(sig * m0), "f"(sig * m1),
                        "f"(sig * m2), "f"(sig * m3) : "memory");
        asm volatile("red.global.add.v4.f32 [%0], {%1, %2, %3, %4};"
                     :: "l"(hd + 32), "f"(sig * n0), "f"(sig * n1),
                        "f"(sig * n2), "f"(sig * n3) : "memory");
    }
}

extern "C" void kernel_launch(void* const* d_in, const int* in_sizes, int n_in,
                              void* d_out, int out_size) {
    const float* node_emb = (const float*)d_in[0];
    const float* edge_emb = (const float*)d_in[1];
    const int*   src      = (const int*)d_in[2];
    const int*   dst      = (const int*)d_in[3];

    int n_nodes = in_sizes[0] / DIM;
    int n_edges = in_sizes[1] / DIM;

    float* h_out  = (float*)d_out;                                // [N, D]
    float* dr_out = (float*)d_out + (long long)n_nodes * DIM;     // [E]

    int h4 = n_nodes * DIM / 4;
    zero_kernel4<<<(h4 + 255) / 256, 256>>>((float4*)h_out, h4);

    int edges_per_block = WARPS_PER_BLOCK * EDGES_PER_WARP;
    int blocks = (n_edges + edges_per_block - 1) / edges_per_block;
    distmult_edge_kernel<<<blocks, THREADS>>>(node_emb, edge_emb, src, dst,
                                              h_out, dr_out, n_edges);
}